// round 6
// baseline (speedup 1.0000x reference)
#include <cuda_runtime.h>
#include <math.h>
#include <stdint.h>

#define LSEQ   4096
#define DMODEL 1024
#define NH     16
#define NKV    4
#define DHEAD  64

// Scratch (no device allocation allowed)
__device__ float g_q[LSEQ * NH * DHEAD];     // 16 MB (tf32 bits after rope_q)
__device__ float g_k[LSEQ * NKV * DHEAD];    // 4 MB  (tf32 bits after rope_k)
__device__ float g_v[LSEQ * NKV * DHEAD];    // 4 MB  (tf32 bits after cvt_v)
__device__ float g_att[LSEQ * NH * DHEAD];   // 16 MB

__device__ __forceinline__ uint32_t f2tf(float f) {
    uint32_t u;
    asm("cvt.rna.tf32.f32 %0, %1;" : "=r"(u) : "f"(f));
    return u;
}

__device__ __forceinline__ void mma_tf32(float c[4],
                                         uint32_t a0, uint32_t a1, uint32_t a2, uint32_t a3,
                                         uint32_t b0, uint32_t b1) {
    asm volatile(
        "mma.sync.aligned.m16n8k8.row.col.f32.tf32.tf32.f32 "
        "{%0,%1,%2,%3}, {%4,%5,%6,%7}, {%8,%9}, {%0,%1,%2,%3};"
        : "+f"(c[0]), "+f"(c[1]), "+f"(c[2]), "+f"(c[3])
        : "r"(a0), "r"(a1), "r"(a2), "r"(a3), "r"(b0), "r"(b1));
}

__device__ __forceinline__ void cp16(uint32_t smem_byte_addr, const void* gptr) {
    asm volatile("cp.async.cg.shared.global [%0], [%1], 16;"
                 :: "r"(smem_byte_addr), "l"(gptr));
}
#define CP_COMMIT() asm volatile("cp.async.commit_group;")
#define CP_WAIT0()  asm volatile("cp.async.wait_group 0;")

// ---------------------------------------------------------------------------
// Pipelined tf32 GEMM body: C[.,N] = A[.,K] @ B[K,N], row-major fp32.
// 128x128 block tile, k-step 32, double-buffered SMEM, reg-staged prefetch.
// ---------------------------------------------------------------------------
#define GEMM_SMEM_BYTES ((2 * 128 * 36 + 2 * 32 * 132) * 4)
#define AS(b, r, c) dsm[(b) * 4608 + (r) * 36 + (c)]
#define BS(b, r, c) dsm[9216 + (b) * 4224 + (r) * 132 + (c)]

__device__ __forceinline__ void gemm_body(const float* __restrict__ A,
                                          const float* __restrict__ B,
                                          float* __restrict__ C,
                                          int N, int K, int m0, int n0) {
    extern __shared__ uint32_t dsm[];
    const int tid  = threadIdx.x;
    const int lane = tid & 31;
    const int warp = tid >> 5;
    const int g = lane >> 2, t = lane & 3;
    const int wm = (warp >> 1) << 5;
    const int wn = (warp & 1) << 6;

    const int ar_r = tid >> 3, ar_c = (tid & 7) << 2;    // A tile: 128x32
    const int br_r = tid >> 5, br_c = (tid & 31) << 2;   // B tile: 32x128

    float4 ar[4], br[4];
#pragma unroll
    for (int i = 0; i < 4; i++) {
        ar[i] = *(const float4*)(A + (size_t)(m0 + ar_r + i * 32) * K + ar_c);
        br[i] = *(const float4*)(B + (size_t)(br_r + i * 8) * N + n0 + br_c);
    }
#pragma unroll
    for (int i = 0; i < 4; i++) {
        *(uint4*)&AS(0, ar_r + i * 32, ar_c) =
            make_uint4(f2tf(ar[i].x), f2tf(ar[i].y), f2tf(ar[i].z), f2tf(ar[i].w));
        *(uint4*)&BS(0, br_r + i * 8, br_c) =
            make_uint4(f2tf(br[i].x), f2tf(br[i].y), f2tf(br[i].z), f2tf(br[i].w));
    }
    __syncthreads();

    float acc[2][8][4];
#pragma unroll
    for (int i = 0; i < 2; i++)
#pragma unroll
        for (int j = 0; j < 8; j++)
#pragma unroll
            for (int q = 0; q < 4; q++) acc[i][j][q] = 0.f;

    for (int k0 = 0; k0 < K; k0 += 32) {
        const int cur = (k0 >> 5) & 1;
        const bool more = (k0 + 32 < K);
        if (more) {
#pragma unroll
            for (int i = 0; i < 4; i++) {
                ar[i] = *(const float4*)(A + (size_t)(m0 + ar_r + i * 32) * K + k0 + 32 + ar_c);
                br[i] = *(const float4*)(B + (size_t)(k0 + 32 + br_r + i * 8) * N + n0 + br_c);
            }
        }
#pragma unroll
        for (int kc = 0; kc < 4; kc++) {
            uint32_t a[2][4];
#pragma unroll
            for (int mt = 0; mt < 2; mt++) {
                int rbm = wm + mt * 16 + g;
                a[mt][0] = AS(cur, rbm, kc * 8 + t);
                a[mt][1] = AS(cur, rbm + 8, kc * 8 + t);
                a[mt][2] = AS(cur, rbm, kc * 8 + t + 4);
                a[mt][3] = AS(cur, rbm + 8, kc * 8 + t + 4);
            }
#pragma unroll
            for (int nt = 0; nt < 8; nt++) {
                uint32_t b0 = BS(cur, kc * 8 + t, wn + nt * 8 + g);
                uint32_t b1 = BS(cur, kc * 8 + t + 4, wn + nt * 8 + g);
                mma_tf32(acc[0][nt], a[0][0], a[0][1], a[0][2], a[0][3], b0, b1);
                mma_tf32(acc[1][nt], a[1][0], a[1][1], a[1][2], a[1][3], b0, b1);
            }
        }
        if (more) {
#pragma unroll
            for (int i = 0; i < 4; i++) {
                *(uint4*)&AS(cur ^ 1, ar_r + i * 32, ar_c) =
                    make_uint4(f2tf(ar[i].x), f2tf(ar[i].y), f2tf(ar[i].z), f2tf(ar[i].w));
                *(uint4*)&BS(cur ^ 1, br_r + i * 8, br_c) =
                    make_uint4(f2tf(br[i].x), f2tf(br[i].y), f2tf(br[i].z), f2tf(br[i].w));
            }
        }
        __syncthreads();
    }

#pragma unroll
    for (int mt = 0; mt < 2; mt++)
#pragma unroll
        for (int nt = 0; nt < 8; nt++) {
            int row = m0 + wm + mt * 16 + g;
            int col = n0 + wn + nt * 8 + 2 * t;
            *(float2*)(C + (size_t)row * N + col)       = make_float2(acc[mt][nt][0], acc[mt][nt][1]);
            *(float2*)(C + (size_t)(row + 8) * N + col) = make_float2(acc[mt][nt][2], acc[mt][nt][3]);
        }
}

// Fused Q/K/V projection: grid.x = 12 n-blocks (8 Q, 2 K, 2 V), grid.y = 32 m-blocks.
__global__ __launch_bounds__(256, 2) void qkv_gemm(const float* __restrict__ x,
                                                   const float* __restrict__ Wq,
                                                   const float* __restrict__ Wk,
                                                   const float* __restrict__ Wv) {
    const int bx = blockIdx.x;
    const float* B; float* C; int N, nb;
    if (bx < 8)       { B = Wq; C = g_q; N = 1024; nb = bx; }
    else if (bx < 10) { B = Wk; C = g_k; N = 256;  nb = bx - 8; }
    else              { B = Wv; C = g_v; N = 256;  nb = bx - 10; }
    gemm_body(x, B, C, N, DMODEL, blockIdx.y << 7, nb << 7);
}

__global__ __launch_bounds__(256, 2) void oproj_gemm(const float* __restrict__ Wo,
                                                     float* __restrict__ out) {
    gemm_body(g_att, Wo, out, DMODEL, DMODEL, blockIdx.y << 7, blockIdx.x << 7);
}

// ---------------------------------------------------------------------------
// RoPE + tf32 pre-conversion.
// rope_q: rotate, scale by DH^-0.5 (exact pow2), store tf32 bits.
// rope_k: rotate, store tf32 bits.  cvt_v: convert in place to tf32 bits.
// ---------------------------------------------------------------------------
__global__ void rope_q(float* __restrict__ buf) {
    int idx = blockIdx.x * blockDim.x + threadIdx.x;
    int i = idx & 31;
    int th = idx >> 5;
    if (th >= LSEQ * NH) return;
    int pos = th >> 4;
    float inv = powf(10000.0f, -(float)i * (1.0f / 32.0f));
    float s, c;
    sincosf((float)pos * inv, &s, &c);
    float* p = buf + (size_t)th * DHEAD;
    float x1 = p[i], x2 = p[i + 32];
    p[i]      = __uint_as_float(f2tf(0.125f * (x1 * c - x2 * s)));
    p[i + 32] = __uint_as_float(f2tf(0.125f * (x2 * c + x1 * s)));
}

__global__ void rope_k(float* __restrict__ buf) {
    int idx = blockIdx.x * blockDim.x + threadIdx.x;
    int i = idx & 31;
    int th = idx >> 5;
    if (th >= LSEQ * NKV) return;
    int pos = th >> 2;
    float inv = powf(10000.0f, -(float)i * (1.0f / 32.0f));
    float s, c;
    sincosf((float)pos * inv, &s, &c);
    float* p = buf + (size_t)th * DHEAD;
    float x1 = p[i], x2 = p[i + 32];
    p[i]      = __uint_as_float(f2tf(x1 * c - x2 * s));
    p[i + 32] = __uint_as_float(f2tf(x2 * c + x1 * s));
}

__global__ void cvt_v(float* __restrict__ buf) {
    int idx = blockIdx.x * blockDim.x + threadIdx.x;
    if (idx < LSEQ * NKV * DHEAD)
        buf[idx] = __uint_as_float(f2tf(buf[idx]));
}

// ---------------------------------------------------------------------------
// Flash attention v3: 128 q-rows/CTA, 4 warps x 32 rows, 2 CTAs/SM.
// Q fragments hoisted into registers; K/V double-buffered via cp.async.
// All operands pre-converted to tf32 bits in global.
// SMEM: Q[128][68] + 2*K[64][68] + 2*V[64][68] = 104448 B.
// ---------------------------------------------------------------------------
#define ATT_SMEM_BYTES (26112 * 4)
#define QS(r, c)      smatt[(r) * 68 + (c)]
#define KS(b, r, c)   smatt[8704 + (b) * 4352 + (r) * 68 + (c)]
#define VS(b, r, c)   smatt[17408 + (b) * 4352 + (r) * 68 + (c)]

__global__ __launch_bounds__(128, 2) void attn_tf32() {
    extern __shared__ uint32_t smatt[];
    const uint32_t sbase = (uint32_t)__cvta_generic_to_shared(smatt);
    const int h = blockIdx.y, kvh = h >> 2;
    const int q0 = blockIdx.x << 7;
    const int tid = threadIdx.x;
    const int lane = tid & 31;
    const int warp = tid >> 5;
    const int g = lane >> 2, t = lane & 3;
    const int rw = warp << 5;           // warp's 32-row base
    const int lb = lane & ~3;
    const int srcA = lb | (t >> 1);
    const int srcB = srcA + 2;
    const bool odd = (t & 1);

    // cp.async staging coordinates
    const int kv_s = tid >> 4;              // 0..7
    const int kv_d = (tid & 15) << 2;       // 0,4,...,60

    // Prologue: stage Q (128x64) + K/V tile 0 (buf 0)
#pragma unroll
    for (int i = 0; i < 16; i++) {
        int r = i * 8 + kv_s;
        cp16(sbase + ((r) * 68 + kv_d) * 4,
             g_q + (size_t)(q0 + r) * (NH * DHEAD) + h * DHEAD + kv_d);
    }
#pragma unroll
    for (int i = 0; i < 8; i++) {
        int s = i * 8 + kv_s;
        size_t ga = (size_t)s * (NKV * DHEAD) + kvh * DHEAD + kv_d;
        cp16(sbase + (8704 + s * 68 + kv_d) * 4, g_k + ga);
        cp16(sbase + (17408 + s * 68 + kv_d) * 4, g_v + ga);
    }
    CP_COMMIT();
    CP_WAIT0();
    __syncthreads();

    // Hoist Q fragments into registers (reused for all 64 key tiles)
    uint32_t qf[2][8][4];
#pragma unroll
    for (int mf = 0; mf < 2; mf++)
#pragma unroll
        for (int kc = 0; kc < 8; kc++) {
            int rbm = rw + mf * 16 + g;
            qf[mf][kc][0] = QS(rbm, kc * 8 + t);
            qf[mf][kc][1] = QS(rbm + 8, kc * 8 + t);
            qf[mf][kc][2] = QS(rbm, kc * 8 + t + 4);
            qf[mf][kc][3] = QS(rbm + 8, kc * 8 + t + 4);
        }

    float mr[2][2], l[2][2];
    float o[2][8][4];
#pragma unroll
    for (int mf = 0; mf < 2; mf++) {
        mr[mf][0] = mr[mf][1] = -1e30f;
        l[mf][0] = l[mf][1] = 0.f;
#pragma unroll
        for (int nt = 0; nt < 8; nt++)
#pragma unroll
            for (int q = 0; q < 4; q++) o[mf][nt][q] = 0.f;
    }

    for (int it = 0; it < 64; it++) {
        const int buf = it & 1;
        if (it > 0) {
            CP_WAIT0();        // tile it arrived
            __syncthreads();   // visible to all; all warps done with tile it-1
        }
        if (it + 1 < 64) {     // async-stage tile it+1 into the other buffer
            const int nb = buf ^ 1;
#pragma unroll
            for (int i = 0; i < 8; i++) {
                int s = i * 8 + kv_s;
                size_t ga = (size_t)((it + 1) * 64 + s) * (NKV * DHEAD) + kvh * DHEAD + kv_d;
                cp16(sbase + (8704 + nb * 4352 + s * 68 + kv_d) * 4, g_k + ga);
                cp16(sbase + (17408 + nb * 4352 + s * 68 + kv_d) * 4, g_v + ga);
            }
            CP_COMMIT();
        }

        // S = Q @ K^T for both m-frags; K b-frags shared
        float sacc[2][8][4];
#pragma unroll
        for (int mf = 0; mf < 2; mf++)
#pragma unroll
            for (int nt = 0; nt < 8; nt++)
#pragma unroll
                for (int q = 0; q < 4; q++) sacc[mf][nt][q] = 0.f;

#pragma unroll
        for (int kc = 0; kc < 8; kc++) {
#pragma unroll
            for (int nt = 0; nt < 8; nt++) {
                uint32_t b0 = KS(buf, nt * 8 + g, kc * 8 + t);
                uint32_t b1 = KS(buf, nt * 8 + g, kc * 8 + t + 4);
                mma_tf32(sacc[0][nt], qf[0][kc][0], qf[0][kc][1], qf[0][kc][2], qf[0][kc][3], b0, b1);
                mma_tf32(sacc[1][nt], qf[1][kc][0], qf[1][kc][1], qf[1][kc][2], qf[1][kc][3], b0, b1);
            }
        }

        // Online softmax per m-frag; overwrite sacc with tf32 bits of exp(S-m)
        float al[2][2];
#pragma unroll
        for (int mf = 0; mf < 2; mf++) {
            float mx0 = -1e30f, mx1 = -1e30f;
#pragma unroll
            for (int nt = 0; nt < 8; nt++) {
                mx0 = fmaxf(mx0, fmaxf(sacc[mf][nt][0], sacc[mf][nt][1]));
                mx1 = fmaxf(mx1, fmaxf(sacc[mf][nt][2], sacc[mf][nt][3]));
            }
            mx0 = fmaxf(mx0, __shfl_xor_sync(0xffffffffu, mx0, 1));
            mx0 = fmaxf(mx0, __shfl_xor_sync(0xffffffffu, mx0, 2));
            mx1 = fmaxf(mx1, __shfl_xor_sync(0xffffffffu, mx1, 1));
            mx1 = fmaxf(mx1, __shfl_xor_sync(0xffffffffu, mx1, 2));
            float mn0 = fmaxf(mr[mf][0], mx0), mn1 = fmaxf(mr[mf][1], mx1);
            al[mf][0] = __expf(mr[mf][0] - mn0);
            al[mf][1] = __expf(mr[mf][1] - mn1);
            mr[mf][0] = mn0; mr[mf][1] = mn1;

            float rs0 = 0.f, rs1 = 0.f;
#pragma unroll
            for (int nt = 0; nt < 8; nt++) {
                float p0 = __expf(sacc[mf][nt][0] - mn0);
                float p1 = __expf(sacc[mf][nt][1] - mn0);
                float p2 = __expf(sacc[mf][nt][2] - mn1);
                float p3 = __expf(sacc[mf][nt][3] - mn1);
                rs0 += p0 + p1; rs1 += p2 + p3;
                sacc[mf][nt][0] = __uint_as_float(f2tf(p0));
                sacc[mf][nt][1] = __uint_as_float(f2tf(p1));
                sacc[mf][nt][2] = __uint_as_float(f2tf(p2));
                sacc[mf][nt][3] = __uint_as_float(f2tf(p3));
            }
            rs0 += __shfl_xor_sync(0xffffffffu, rs0, 1);
            rs0 += __shfl_xor_sync(0xffffffffu, rs0, 2);
            rs1 += __shfl_xor_sync(0xffffffffu, rs1, 1);
            rs1 += __shfl_xor_sync(0xffffffffu, rs1, 2);
            l[mf][0] = l[mf][0] * al[mf][0] + rs0;
            l[mf][1] = l[mf][1] * al[mf][1] + rs1;
#pragma unroll
            for (int nt = 0; nt < 8; nt++) {
                o[mf][nt][0] *= al[mf][0]; o[mf][nt][1] *= al[mf][0];
                o[mf][nt][2] *= al[mf][1]; o[mf][nt][3] *= al[mf][1];
            }
        }

        // O += P @ V ; P A-frags from sacc C-layout via shuffles; V b shared
#pragma unroll
        for (int kc = 0; kc < 8; kc++) {
            uint32_t a[2][4];
#pragma unroll
            for (int mf = 0; mf < 2; mf++) {
                uint32_t p0 = __float_as_uint(sacc[mf][kc][0]);
                uint32_t p1 = __float_as_uint(sacc[mf][kc][1]);
                uint32_t p2 = __float_as_uint(sacc[mf][kc][2]);
                uint32_t p3 = __float_as_uint(sacc[mf][kc][3]);
                uint32_t sA0 = __shfl_sync(0xffffffffu, p0, srcA);
                uint32_t sA1 = __shfl_sync(0xffffffffu, p1, srcA);
                uint32_t sA2 = __shfl_sync(0xffffffffu, p2, srcA);
                uint32_t sA3 = __shfl_sync(0xffffffffu, p3, srcA);
                uint32_t sB0 = __shfl_sync(0xffffffffu, p0, srcB);
                uint32_t sB1 = __shfl_sync(0xffffffffu, p1, srcB);
                uint32_t sB2 = __shfl_sync(0xffffffffu, p2, srcB);
                uint32_t sB3 = __shfl_sync(0xffffffffu, p3, srcB);
                a[mf][0] = odd ? sA1 : sA0;
                a[mf][1] = odd ? sA3 : sA2;
                a[mf][2] = odd ? sB1 : sB0;
                a[mf][3] = odd ? sB3 : sB2;
            }
#pragma unroll
            for (int nt = 0; nt < 8; nt++) {
                uint32_t b0 = VS(buf, kc * 8 + t, nt * 8 + g);
                uint32_t b1 = VS(buf, kc * 8 + t + 4, nt * 8 + g);
                mma_tf32(o[0][nt], a[0][0], a[0][1], a[0][2], a[0][3], b0, b1);
                mma_tf32(o[1][nt], a[1][0], a[1][1], a[1][2], a[1][3], b0, b1);
            }
        }
    }

    // l already holds full row sums (quad-reduced every tile)
#pragma unroll
    for (int mf = 0; mf < 2; mf++) {
        float inv0 = 1.0f / l[mf][0], inv1 = 1.0f / l[mf][1];
        int row = q0 + rw + mf * 16 + g;
#pragma unroll
        for (int nt = 0; nt < 8; nt++) {
            int col = h * DHEAD + nt * 8 + 2 * t;
            *(float2*)(g_att + (size_t)row * (NH * DHEAD) + col) =
                make_float2(o[mf][nt][0] * inv0, o[mf][nt][1] * inv0);
            *(float2*)(g_att + (size_t)(row + 8) * (NH * DHEAD) + col) =
                make_float2(o[mf][nt][2] * inv1, o[mf][nt][3] * inv1);
        }
    }
}

// ---------------------------------------------------------------------------
extern "C" void kernel_launch(void* const* d_in, const int* in_sizes, int n_in,
                              void* d_out, int out_size) {
    const float* x  = (const float*)d_in[0];
    const float* Wq = (const float*)d_in[1];
    const float* Wk = (const float*)d_in[2];
    const float* Wv = (const float*)d_in[3];
    const float* Wo = (const float*)d_in[4];
    float* out = (float*)d_out;

    float *qp, *kp, *vp;
    cudaGetSymbolAddress((void**)&qp, g_q);
    cudaGetSymbolAddress((void**)&kp, g_k);
    cudaGetSymbolAddress((void**)&vp, g_v);

    cudaFuncSetAttribute(qkv_gemm,   cudaFuncAttributeMaxDynamicSharedMemorySize, GEMM_SMEM_BYTES);
    cudaFuncSetAttribute(oproj_gemm, cudaFuncAttributeMaxDynamicSharedMemorySize, GEMM_SMEM_BYTES);
    cudaFuncSetAttribute(attn_tf32,  cudaFuncAttributeMaxDynamicSharedMemorySize, ATT_SMEM_BYTES);

    qkv_gemm<<<dim3(12, 32), 256, GEMM_SMEM_BYTES>>>(x, Wq, Wk, Wv);
    rope_q<<<(LSEQ * NH * 32 + 255) / 256, 256>>>(qp);
    rope_k<<<(LSEQ * NKV * 32 + 255) / 256, 256>>>(kp);
    cvt_v<<<(LSEQ * NKV * DHEAD + 255) / 256, 256>>>(vp);
    attn_tf32<<<dim3(LSEQ / 128, NH), 128, ATT_SMEM_BYTES>>>();
    oproj_gemm<<<dim3(DMODEL / 128, LSEQ / 128), 256, GEMM_SMEM_BYTES>>>(Wo, out);
}

// round 7
// speedup vs baseline: 1.0768x; 1.0768x over previous
#include <cuda_runtime.h>
#include <math.h>
#include <stdint.h>

#define LSEQ   4096
#define DMODEL 1024
#define NH     16
#define NKV    4
#define DHEAD  64

// Scratch (no device allocation allowed)
__device__ float g_q[LSEQ * NH * DHEAD];     // tf32 bits after rope_q
__device__ float g_k[LSEQ * NKV * DHEAD];    // tf32 bits after rope_k
__device__ float g_v[LSEQ * NKV * DHEAD];    // tf32 bits after cvt_v
__device__ float g_att[LSEQ * NH * DHEAD];

__device__ __forceinline__ uint32_t f2tf(float f) {
    uint32_t u;
    asm("cvt.rna.tf32.f32 %0, %1;" : "=r"(u) : "f"(f));
    return u;
}

__device__ __forceinline__ void mma_tf32(float c[4],
                                         uint32_t a0, uint32_t a1, uint32_t a2, uint32_t a3,
                                         uint32_t b0, uint32_t b1) {
    asm volatile(
        "mma.sync.aligned.m16n8k8.row.col.f32.tf32.tf32.f32 "
        "{%0,%1,%2,%3}, {%4,%5,%6,%7}, {%8,%9}, {%0,%1,%2,%3};"
        : "+f"(c[0]), "+f"(c[1]), "+f"(c[2]), "+f"(c[3])
        : "r"(a0), "r"(a1), "r"(a2), "r"(a3), "r"(b0), "r"(b1));
}

__device__ __forceinline__ void cp16(uint32_t smem_byte_addr, const void* gptr) {
    asm volatile("cp.async.cg.shared.global [%0], [%1], 16;"
                 :: "r"(smem_byte_addr), "l"(gptr));
}
#define CP_COMMIT() asm volatile("cp.async.commit_group;")
#define CP_WAIT0()  asm volatile("cp.async.wait_group 0;")

// ---------------------------------------------------------------------------
// Pipelined tf32 GEMM body: C[.,N] = A[.,K] @ B[K,N], row-major fp32.
// 128x128 block tile, k-step 32, double-buffered SMEM, reg-staged prefetch.
// ---------------------------------------------------------------------------
#define GEMM_SMEM_BYTES ((2 * 128 * 36 + 2 * 32 * 132) * 4)
#define AS(b, r, c) dsm[(b) * 4608 + (r) * 36 + (c)]
#define BS(b, r, c) dsm[9216 + (b) * 4224 + (r) * 132 + (c)]

__device__ __forceinline__ void gemm_body(const float* __restrict__ A,
                                          const float* __restrict__ B,
                                          float* __restrict__ C,
                                          int N, int K, int m0, int n0) {
    extern __shared__ uint32_t dsm[];
    const int tid  = threadIdx.x;
    const int lane = tid & 31;
    const int warp = tid >> 5;
    const int g = lane >> 2, t = lane & 3;
    const int wm = (warp >> 1) << 5;
    const int wn = (warp & 1) << 6;

    const int ar_r = tid >> 3, ar_c = (tid & 7) << 2;    // A tile: 128x32
    const int br_r = tid >> 5, br_c = (tid & 31) << 2;   // B tile: 32x128

    float4 ar[4], br[4];
#pragma unroll
    for (int i = 0; i < 4; i++) {
        ar[i] = *(const float4*)(A + (size_t)(m0 + ar_r + i * 32) * K + ar_c);
        br[i] = *(const float4*)(B + (size_t)(br_r + i * 8) * N + n0 + br_c);
    }
#pragma unroll
    for (int i = 0; i < 4; i++) {
        *(uint4*)&AS(0, ar_r + i * 32, ar_c) =
            make_uint4(f2tf(ar[i].x), f2tf(ar[i].y), f2tf(ar[i].z), f2tf(ar[i].w));
        *(uint4*)&BS(0, br_r + i * 8, br_c) =
            make_uint4(f2tf(br[i].x), f2tf(br[i].y), f2tf(br[i].z), f2tf(br[i].w));
    }
    __syncthreads();

    float acc[2][8][4];
#pragma unroll
    for (int i = 0; i < 2; i++)
#pragma unroll
        for (int j = 0; j < 8; j++)
#pragma unroll
            for (int q = 0; q < 4; q++) acc[i][j][q] = 0.f;

    for (int k0 = 0; k0 < K; k0 += 32) {
        const int cur = (k0 >> 5) & 1;
        const bool more = (k0 + 32 < K);
        if (more) {
#pragma unroll
            for (int i = 0; i < 4; i++) {
                ar[i] = *(const float4*)(A + (size_t)(m0 + ar_r + i * 32) * K + k0 + 32 + ar_c);
                br[i] = *(const float4*)(B + (size_t)(k0 + 32 + br_r + i * 8) * N + n0 + br_c);
            }
        }
#pragma unroll
        for (int kc = 0; kc < 4; kc++) {
            uint32_t a[2][4];
#pragma unroll
            for (int mt = 0; mt < 2; mt++) {
                int rbm = wm + mt * 16 + g;
                a[mt][0] = AS(cur, rbm, kc * 8 + t);
                a[mt][1] = AS(cur, rbm + 8, kc * 8 + t);
                a[mt][2] = AS(cur, rbm, kc * 8 + t + 4);
                a[mt][3] = AS(cur, rbm + 8, kc * 8 + t + 4);
            }
#pragma unroll
            for (int nt = 0; nt < 8; nt++) {
                uint32_t b0 = BS(cur, kc * 8 + t, wn + nt * 8 + g);
                uint32_t b1 = BS(cur, kc * 8 + t + 4, wn + nt * 8 + g);
                mma_tf32(acc[0][nt], a[0][0], a[0][1], a[0][2], a[0][3], b0, b1);
                mma_tf32(acc[1][nt], a[1][0], a[1][1], a[1][2], a[1][3], b0, b1);
            }
        }
        if (more) {
#pragma unroll
            for (int i = 0; i < 4; i++) {
                *(uint4*)&AS(cur ^ 1, ar_r + i * 32, ar_c) =
                    make_uint4(f2tf(ar[i].x), f2tf(ar[i].y), f2tf(ar[i].z), f2tf(ar[i].w));
                *(uint4*)&BS(cur ^ 1, br_r + i * 8, br_c) =
                    make_uint4(f2tf(br[i].x), f2tf(br[i].y), f2tf(br[i].z), f2tf(br[i].w));
            }
        }
        __syncthreads();
    }

#pragma unroll
    for (int mt = 0; mt < 2; mt++)
#pragma unroll
        for (int nt = 0; nt < 8; nt++) {
            int row = m0 + wm + mt * 16 + g;
            int col = n0 + wn + nt * 8 + 2 * t;
            *(float2*)(C + (size_t)row * N + col)       = make_float2(acc[mt][nt][0], acc[mt][nt][1]);
            *(float2*)(C + (size_t)(row + 8) * N + col) = make_float2(acc[mt][nt][2], acc[mt][nt][3]);
        }
}

// Fused Q/K/V projection: grid.x = 12 n-blocks (8 Q, 2 K, 2 V), grid.y = 32 m-blocks.
__global__ __launch_bounds__(256, 2) void qkv_gemm(const float* __restrict__ x,
                                                   const float* __restrict__ Wq,
                                                   const float* __restrict__ Wk,
                                                   const float* __restrict__ Wv) {
    const int bx = blockIdx.x;
    const float* B; float* C; int N, nb;
    if (bx < 8)       { B = Wq; C = g_q; N = 1024; nb = bx; }
    else if (bx < 10) { B = Wk; C = g_k; N = 256;  nb = bx - 8; }
    else              { B = Wv; C = g_v; N = 256;  nb = bx - 10; }
    gemm_body(x, B, C, N, DMODEL, blockIdx.y << 7, nb << 7);
}

__global__ __launch_bounds__(256, 2) void oproj_gemm(const float* __restrict__ Wo,
                                                     float* __restrict__ out) {
    gemm_body(g_att, Wo, out, DMODEL, DMODEL, blockIdx.y << 7, blockIdx.x << 7);
}

// ---------------------------------------------------------------------------
// RoPE + tf32 pre-conversion.
// ---------------------------------------------------------------------------
__global__ void rope_q(float* __restrict__ buf) {
    int idx = blockIdx.x * blockDim.x + threadIdx.x;
    int i = idx & 31;
    int th = idx >> 5;
    if (th >= LSEQ * NH) return;
    int pos = th >> 4;
    float inv = powf(10000.0f, -(float)i * (1.0f / 32.0f));
    float s, c;
    sincosf((float)pos * inv, &s, &c);
    float* p = buf + (size_t)th * DHEAD;
    float x1 = p[i], x2 = p[i + 32];
    p[i]      = __uint_as_float(f2tf(0.125f * (x1 * c - x2 * s)));
    p[i + 32] = __uint_as_float(f2tf(0.125f * (x2 * c + x1 * s)));
}

__global__ void rope_k(float* __restrict__ buf) {
    int idx = blockIdx.x * blockDim.x + threadIdx.x;
    int i = idx & 31;
    int th = idx >> 5;
    if (th >= LSEQ * NKV) return;
    int pos = th >> 2;
    float inv = powf(10000.0f, -(float)i * (1.0f / 32.0f));
    float s, c;
    sincosf((float)pos * inv, &s, &c);
    float* p = buf + (size_t)th * DHEAD;
    float x1 = p[i], x2 = p[i + 32];
    p[i]      = __uint_as_float(f2tf(x1 * c - x2 * s));
    p[i + 32] = __uint_as_float(f2tf(x2 * c + x1 * s));
}

__global__ void cvt_v(float* __restrict__ buf) {
    int idx = blockIdx.x * blockDim.x + threadIdx.x;
    if (idx < LSEQ * NKV * DHEAD)
        buf[idx] = __uint_as_float(f2tf(buf[idx]));
}

// ---------------------------------------------------------------------------
// Flash attention v4 (R5 shape + async staging):
// 256 q-rows/CTA, 8 warps x 32 rows (2 x 16-row m-frags), grid (16,16).
// Operands pre-converted to tf32 in global; K/V double-buffered via cp.async;
// ONE __syncthreads per key tile. Q stays in SMEM (register budget).
// SMEM words: Q 256*68=17408, K 2*64*68=8704, V 8704 -> 139264 bytes.
// ---------------------------------------------------------------------------
#define ATT_SMEM_BYTES (34816 * 4)
#define QS(r, c)     smatt[(r) * 68 + (c)]
#define KS(b, r, c)  smatt[17408 + (b) * 4352 + (r) * 68 + (c)]
#define VS(b, r, c)  smatt[26112 + (b) * 4352 + (r) * 68 + (c)]

__global__ __launch_bounds__(256, 1) void attn_tf32() {
    extern __shared__ uint32_t smatt[];
    const uint32_t sbase = (uint32_t)__cvta_generic_to_shared(smatt);
    const int h = blockIdx.y, kvh = h >> 2;
    const int q0 = blockIdx.x << 8;
    const int tid = threadIdx.x;
    const int lane = tid & 31;
    const int warp = tid >> 5;
    const int g = lane >> 2, t = lane & 3;
    const int rw = warp << 5;
    const int lb = lane & ~3;
    const int srcA = lb | (t >> 1);
    const int srcB = srcA + 2;
    const bool odd = (t & 1);

    // Prologue: async-stage Q (256x64) and K/V tile 0 into buffer 0.
#pragma unroll
    for (int i = 0; i < 16; i++) {
        int lin = i * 256 + tid;
        int r = lin >> 4, c4 = (lin & 15) << 2;
        cp16(sbase + (r * 68 + c4) * 4,
             g_q + (size_t)(q0 + r) * (NH * DHEAD) + h * DHEAD + c4);
    }
#pragma unroll
    for (int i = 0; i < 4; i++) {
        int lin = i * 256 + tid;
        int s = lin >> 4, d4 = (lin & 15) << 2;
        size_t ga = (size_t)s * (NKV * DHEAD) + kvh * DHEAD + d4;
        cp16(sbase + (17408 + s * 68 + d4) * 4, g_k + ga);
        cp16(sbase + (26112 + s * 68 + d4) * 4, g_v + ga);
    }
    CP_COMMIT();

    float mr[2][2], l[2][2];
    float o[2][8][4];
#pragma unroll
    for (int mf = 0; mf < 2; mf++) {
        mr[mf][0] = mr[mf][1] = -1e30f;
        l[mf][0] = l[mf][1] = 0.f;
#pragma unroll
        for (int nt = 0; nt < 8; nt++)
#pragma unroll
            for (int q = 0; q < 4; q++) o[mf][nt][q] = 0.f;
    }

    for (int it = 0; it < 64; it++) {
        const int buf = it & 1;
        CP_WAIT0();          // tile it (and, for it=0, Q) has landed
        __syncthreads();     // all warps done with buf from tile it-1; data visible

        if (it + 1 < 64) {   // async-prefetch tile it+1 into the other buffer
            const int nb = buf ^ 1;
#pragma unroll
            for (int i = 0; i < 4; i++) {
                int lin = i * 256 + tid;
                int s = lin >> 4, d4 = (lin & 15) << 2;
                size_t ga = (size_t)((it + 1) * 64 + s) * (NKV * DHEAD) + kvh * DHEAD + d4;
                cp16(sbase + (17408 + nb * 4352 + s * 68 + d4) * 4, g_k + ga);
                cp16(sbase + (26112 + nb * 4352 + s * 68 + d4) * 4, g_v + ga);
            }
            CP_COMMIT();
        }

        // S = Q @ K^T for both m-frags; K b-frags shared
        float sacc[2][8][4];
#pragma unroll
        for (int mf = 0; mf < 2; mf++)
#pragma unroll
            for (int nt = 0; nt < 8; nt++)
#pragma unroll
                for (int q = 0; q < 4; q++) sacc[mf][nt][q] = 0.f;

#pragma unroll
        for (int kc = 0; kc < 8; kc++) {
            uint32_t a[2][4];
#pragma unroll
            for (int mf = 0; mf < 2; mf++) {
                int rbm = rw + mf * 16 + g;
                a[mf][0] = QS(rbm, kc * 8 + t);
                a[mf][1] = QS(rbm + 8, kc * 8 + t);
                a[mf][2] = QS(rbm, kc * 8 + t + 4);
                a[mf][3] = QS(rbm + 8, kc * 8 + t + 4);
            }
#pragma unroll
            for (int nt = 0; nt < 8; nt++) {
                uint32_t b0 = KS(buf, nt * 8 + g, kc * 8 + t);
                uint32_t b1 = KS(buf, nt * 8 + g, kc * 8 + t + 4);
                mma_tf32(sacc[0][nt], a[0][0], a[0][1], a[0][2], a[0][3], b0, b1);
                mma_tf32(sacc[1][nt], a[1][0], a[1][1], a[1][2], a[1][3], b0, b1);
            }
        }

        // Online softmax per m-frag; overwrite sacc with tf32 bits of exp(S-m)
        float al[2][2];
#pragma unroll
        for (int mf = 0; mf < 2; mf++) {
            float mx0 = -1e30f, mx1 = -1e30f;
#pragma unroll
            for (int nt = 0; nt < 8; nt++) {
                mx0 = fmaxf(mx0, fmaxf(sacc[mf][nt][0], sacc[mf][nt][1]));
                mx1 = fmaxf(mx1, fmaxf(sacc[mf][nt][2], sacc[mf][nt][3]));
            }
            mx0 = fmaxf(mx0, __shfl_xor_sync(0xffffffffu, mx0, 1));
            mx0 = fmaxf(mx0, __shfl_xor_sync(0xffffffffu, mx0, 2));
            mx1 = fmaxf(mx1, __shfl_xor_sync(0xffffffffu, mx1, 1));
            mx1 = fmaxf(mx1, __shfl_xor_sync(0xffffffffu, mx1, 2));
            float mn0 = fmaxf(mr[mf][0], mx0), mn1 = fmaxf(mr[mf][1], mx1);
            al[mf][0] = __expf(mr[mf][0] - mn0);
            al[mf][1] = __expf(mr[mf][1] - mn1);
            mr[mf][0] = mn0; mr[mf][1] = mn1;

            float rs0 = 0.f, rs1 = 0.f;
#pragma unroll
            for (int nt = 0; nt < 8; nt++) {
                float p0 = __expf(sacc[mf][nt][0] - mn0);
                float p1 = __expf(sacc[mf][nt][1] - mn0);
                float p2 = __expf(sacc[mf][nt][2] - mn1);
                float p3 = __expf(sacc[mf][nt][3] - mn1);
                rs0 += p0 + p1; rs1 += p2 + p3;
                sacc[mf][nt][0] = __uint_as_float(f2tf(p0));
                sacc[mf][nt][1] = __uint_as_float(f2tf(p1));
                sacc[mf][nt][2] = __uint_as_float(f2tf(p2));
                sacc[mf][nt][3] = __uint_as_float(f2tf(p3));
            }
            rs0 += __shfl_xor_sync(0xffffffffu, rs0, 1);
            rs0 += __shfl_xor_sync(0xffffffffu, rs0, 2);
            rs1 += __shfl_xor_sync(0xffffffffu, rs1, 1);
            rs1 += __shfl_xor_sync(0xffffffffu, rs1, 2);
            l[mf][0] = l[mf][0] * al[mf][0] + rs0;
            l[mf][1] = l[mf][1] * al[mf][1] + rs1;
#pragma unroll
            for (int nt = 0; nt < 8; nt++) {
                o[mf][nt][0] *= al[mf][0]; o[mf][nt][1] *= al[mf][0];
                o[mf][nt][2] *= al[mf][1]; o[mf][nt][3] *= al[mf][1];
            }
        }

        // O += P @ V ; P A-frags from sacc C-layout via shuffles; V b shared
#pragma unroll
        for (int kc = 0; kc < 8; kc++) {
            uint32_t a[2][4];
#pragma unroll
            for (int mf = 0; mf < 2; mf++) {
                uint32_t p0 = __float_as_uint(sacc[mf][kc][0]);
                uint32_t p1 = __float_as_uint(sacc[mf][kc][1]);
                uint32_t p2 = __float_as_uint(sacc[mf][kc][2]);
                uint32_t p3 = __float_as_uint(sacc[mf][kc][3]);
                uint32_t sA0 = __shfl_sync(0xffffffffu, p0, srcA);
                uint32_t sA1 = __shfl_sync(0xffffffffu, p1, srcA);
                uint32_t sA2 = __shfl_sync(0xffffffffu, p2, srcA);
                uint32_t sA3 = __shfl_sync(0xffffffffu, p3, srcA);
                uint32_t sB0 = __shfl_sync(0xffffffffu, p0, srcB);
                uint32_t sB1 = __shfl_sync(0xffffffffu, p1, srcB);
                uint32_t sB2 = __shfl_sync(0xffffffffu, p2, srcB);
                uint32_t sB3 = __shfl_sync(0xffffffffu, p3, srcB);
                a[mf][0] = odd ? sA1 : sA0;
                a[mf][1] = odd ? sA3 : sA2;
                a[mf][2] = odd ? sB1 : sB0;
                a[mf][3] = odd ? sB3 : sB2;
            }
#pragma unroll
            for (int nt = 0; nt < 8; nt++) {
                uint32_t b0 = VS(buf, kc * 8 + t, nt * 8 + g);
                uint32_t b1 = VS(buf, kc * 8 + t + 4, nt * 8 + g);
                mma_tf32(o[0][nt], a[0][0], a[0][1], a[0][2], a[0][3], b0, b1);
                mma_tf32(o[1][nt], a[1][0], a[1][1], a[1][2], a[1][3], b0, b1);
            }
        }
    }

    // l already holds full row sums (quad-reduced every tile)
#pragma unroll
    for (int mf = 0; mf < 2; mf++) {
        float inv0 = 1.0f / l[mf][0], inv1 = 1.0f / l[mf][1];
        int row = q0 + rw + mf * 16 + g;
#pragma unroll
        for (int nt = 0; nt < 8; nt++) {
            int col = h * DHEAD + nt * 8 + 2 * t;
            *(float2*)(g_att + (size_t)row * (NH * DHEAD) + col) =
                make_float2(o[mf][nt][0] * inv0, o[mf][nt][1] * inv0);
            *(float2*)(g_att + (size_t)(row + 8) * (NH * DHEAD) + col) =
                make_float2(o[mf][nt][2] * inv1, o[mf][nt][3] * inv1);
        }
    }
}

// ---------------------------------------------------------------------------
extern "C" void kernel_launch(void* const* d_in, const int* in_sizes, int n_in,
                              void* d_out, int out_size) {
    const float* x  = (const float*)d_in[0];
    const float* Wq = (const float*)d_in[1];
    const float* Wk = (const float*)d_in[2];
    const float* Wv = (const float*)d_in[3];
    const float* Wo = (const float*)d_in[4];
    float* out = (float*)d_out;

    float *qp, *kp, *vp;
    cudaGetSymbolAddress((void**)&qp, g_q);
    cudaGetSymbolAddress((void**)&kp, g_k);
    cudaGetSymbolAddress((void**)&vp, g_v);

    cudaFuncSetAttribute(qkv_gemm,   cudaFuncAttributeMaxDynamicSharedMemorySize, GEMM_SMEM_BYTES);
    cudaFuncSetAttribute(oproj_gemm, cudaFuncAttributeMaxDynamicSharedMemorySize, GEMM_SMEM_BYTES);
    cudaFuncSetAttribute(attn_tf32,  cudaFuncAttributeMaxDynamicSharedMemorySize, ATT_SMEM_BYTES);

    qkv_gemm<<<dim3(12, 32), 256, GEMM_SMEM_BYTES>>>(x, Wq, Wk, Wv);
    rope_q<<<(LSEQ * NH * 32 + 255) / 256, 256>>>(qp);
    rope_k<<<(LSEQ * NKV * 32 + 255) / 256, 256>>>(kp);
    cvt_v<<<(LSEQ * NKV * DHEAD + 255) / 256, 256>>>(vp);
    attn_tf32<<<dim3(LSEQ / 256, NH), 256, ATT_SMEM_BYTES>>>();
    oproj_gemm<<<dim3(DMODEL / 128, LSEQ / 128), 256, GEMM_SMEM_BYTES>>>(Wo, out);
}